// round 12
// baseline (speedup 1.0000x reference)
#include <cuda_runtime.h>
#include <cuda_bf16.h>

#define FEAT 128
#define MAX_NODES 50000

typedef unsigned int u32;

// ---------------- device scratch ----------------
static __device__ float g_agg[(size_t)MAX_NODES * FEAT];
// weight fragments, u32-packed per mma.m16n8k16 B-lane layout:
// idx = (((chunk*2+split)*4 + ks)*16 + nf)*64 + lane*2 + r
static __device__ __align__(16) u32 g_w1a_f[32768];  // K=256: 4 chunks
static __device__ __align__(16) u32 g_w1b_f[16384];  // K=128: 2 chunks
static __device__ __align__(16) u32 g_w2a_f[16384];
static __device__ __align__(16) u32 g_w2b_f[16384];

// ---- smem geometry (dynamic, bytes) ----
// A bf16 tile: hi @0 (128 rows x 144B), lo @18432  -> 36864
// fp32 stage:  @36864, 128 rows x 272B = 34816     -> 71680
// weights:     wb0 @71680 (16KB), wb1 @88064 (16KB)-> 104448
// hidden fragments (64KB) alias [0..65536) during layer 2.
// scatter buffer (128 rows x 528B = 67584) aliases [0..67584) after layer 2.
#define A_STRIDE   144
#define A_TILEB    18432
#define STG_OFF    36864
#define STG_STRIDE 272
#define WB0_OFF    71680
#define WB1_OFF    88064
#define SCAT_STRIDE 528
#define DYN_BYTES  104448

// ---------------- helpers ----------------
__device__ __forceinline__ u32 smem_u32(const void* p) {
    u32 a;
    asm("{ .reg .u64 t; cvta.to.shared.u64 t, %1; cvt.u32.u64 %0, t; }" : "=r"(a) : "l"(p));
    return a;
}
__device__ __forceinline__ u32 lds32(u32 a) {
    u32 v;
    asm volatile("ld.shared.b32 %0, [%1];" : "=r"(v) : "r"(a));
    return v;
}
__device__ __forceinline__ void lds64(u32 a, u32& x, u32& y) {
    asm volatile("ld.shared.v2.b32 {%0,%1}, [%2];" : "=r"(x), "=r"(y) : "r"(a));
}
__device__ __forceinline__ void lds128(u32 a, u32* r) {
    asm volatile("ld.shared.v4.b32 {%0,%1,%2,%3}, [%4];"
                 : "=r"(r[0]), "=r"(r[1]), "=r"(r[2]), "=r"(r[3]) : "r"(a));
}
__device__ __forceinline__ void sts32(u32 a, u32 v) {
    asm volatile("st.shared.b32 [%0], %1;" ::"r"(a), "r"(v));
}
__device__ __forceinline__ void sts64f(u32 a, float x, float y) {
    asm volatile("st.shared.v2.f32 [%0], {%1,%2};" ::"r"(a), "f"(x), "f"(y));
}
__device__ __forceinline__ void sts128(u32 a, const u32* r) {
    asm volatile("st.shared.v4.b32 [%0], {%1,%2,%3,%4};" ::"r"(a), "r"(r[0]), "r"(r[1]),
                 "r"(r[2]), "r"(r[3]));
}
__device__ __forceinline__ void red_v4(float* p, float a, float b, float c, float d) {
    asm volatile("red.global.add.v4.f32 [%0], {%1,%2,%3,%4};" ::"l"(p), "f"(a), "f"(b),
                 "f"(c), "f"(d)
                 : "memory");
}

__device__ __forceinline__ void mma16816(float c[4], const u32 a[4], u32 b0, u32 b1) {
    asm volatile(
        "mma.sync.aligned.m16n8k16.row.col.f32.bf16.bf16.f32 "
        "{%0,%1,%2,%3}, {%4,%5,%6,%7}, {%8,%9}, {%0,%1,%2,%3};"
        : "+f"(c[0]), "+f"(c[1]), "+f"(c[2]), "+f"(c[3])
        : "r"(a[0]), "r"(a[1]), "r"(a[2]), "r"(a[3]), "r"(b0), "r"(b1));
}

// fp32 pair -> packed bf16x2 hi + bf16x2 lo (x in low half)
__device__ __forceinline__ void split2(float x, float y, u32& h, u32& l) {
    asm("cvt.rn.bf16x2.f32 %0, %1, %2;" : "=r"(h) : "f"(y), "f"(x));
    float rx = x - __uint_as_float(h << 16);
    float ry = y - __uint_as_float(h & 0xFFFF0000u);
    asm("cvt.rn.bf16x2.f32 %0, %1, %2;" : "=r"(l) : "f"(ry), "f"(rx));
}

// ---- cp.async staging: each thread stages 32 fp32 (its own convert slice) ----
__device__ __forceinline__ void stage_row(const float* __restrict__ sp, u32 sd) {
#pragma unroll
    for (int q = 0; q < 8; q++) {
        asm volatile("cp.async.cg.shared.global [%0], [%1], 16;" ::"r"(sd + q * 16),
                     "l"(sp + q * 4));
    }
    asm volatile("cp.async.commit_group;");
}

// convert own staged 32 fp32 -> hi/lo bf16 in A tile (smem -> smem)
__device__ __forceinline__ void convert_own(u32 ss, u32 dhi) {
#pragma unroll
    for (int q = 0; q < 8; q++) {
        u32 w[4];
        lds128(ss + q * 16, w);
        u32 h0, l0, h1, l1;
        split2(__uint_as_float(w[0]), __uint_as_float(w[1]), h0, l0);
        split2(__uint_as_float(w[2]), __uint_as_float(w[3]), h1, l1);
        sts32(dhi + q * 8, h0);
        sts32(dhi + q * 8 + 4, h1);
        sts32(dhi + A_TILEB + q * 8, l0);
        sts32(dhi + A_TILEB + q * 8 + 4, l1);
    }
}

// async-copy one 16KB weight split-tile global -> smem (256 threads)
__device__ __forceinline__ void cp_w16(const u32* __restrict__ g, u32 sB, int tid) {
#pragma unroll
    for (int i = 0; i < 4; i++) {
        u32 d = sB + (u32)(tid + i * 256) * 16;
        const u32* s = g + (tid + i * 256) * 4;
        asm volatile("cp.async.cg.shared.global [%0], [%1], 16;" ::"r"(d), "l"(s));
    }
    asm volatile("cp.async.commit_group;");
}
#define CP_WAIT0() asm volatile("cp.async.wait_group 0;" ::: "memory")

// ---- fused layer-1 GEMM chunk ----
__device__ __forceinline__ void g1_fused(u32 aHi, u32 wbh, u32 wbl, float (*acc)[4][4],
                                         int lane, int wc) {
    const u32 arow = aHi + (u32)(lane >> 2) * A_STRIDE + (lane & 3) * 4;
    const u32 blh = wbh + (u32)wc * 1024 + lane * 8;
    const u32 bll = wbl + (u32)wc * 1024 + lane * 8;
#pragma unroll
    for (int ks = 0; ks < 4; ks++) {
        u32 bh[4][2], bl[4][2];
#pragma unroll
        for (int nf = 0; nf < 4; nf++) {
            lds64(blh + ks * 4096 + nf * 256, bh[nf][0], bh[nf][1]);
            lds64(bll + ks * 4096 + nf * 256, bl[nf][0], bl[nf][1]);
        }
#pragma unroll
        for (int mg = 0; mg < 2; mg++) {
            u32 ah[2][4], al[2][4];
#pragma unroll
            for (int m = 0; m < 2; m++) {
                u32 ab = arow + (mg * 2 + m) * (16 * A_STRIDE) + ks * 32;
                ah[m][0] = lds32(ab);
                ah[m][1] = lds32(ab + 8 * A_STRIDE);
                ah[m][2] = lds32(ab + 16);
                ah[m][3] = lds32(ab + 8 * A_STRIDE + 16);
                u32 ao = ab + A_TILEB;
                al[m][0] = lds32(ao);
                al[m][1] = lds32(ao + 8 * A_STRIDE);
                al[m][2] = lds32(ao + 16);
                al[m][3] = lds32(ao + 8 * A_STRIDE + 16);
            }
#pragma unroll
            for (int m = 0; m < 2; m++)
#pragma unroll
                for (int nf = 0; nf < 4; nf++)
                    mma16816(acc[mg * 2 + m][nf], ah[m], bh[nf][0], bh[nf][1]);
#pragma unroll
            for (int m = 0; m < 2; m++)
#pragma unroll
                for (int nf = 0; nf < 4; nf++)
                    mma16816(acc[mg * 2 + m][nf], ah[m], bl[nf][0], bl[nf][1]);
#pragma unroll
            for (int m = 0; m < 2; m++)
#pragma unroll
                for (int nf = 0; nf < 4; nf++)
                    mma16816(acc[mg * 2 + m][nf], al[m], bh[nf][0], bh[nf][1]);
        }
    }
}

// ---- fused layer-2 GEMM chunk: A from hidden fragments (LDS.128) ----
__device__ __forceinline__ void g2_fused(u32 hb, u32 wbh, u32 wbl, float (*acc)[4][4],
                                         int lane, int wr, int wc, int kg0) {
    const u32 blh = wbh + (u32)wc * 1024 + lane * 8;
    const u32 bll = wbl + (u32)wc * 1024 + lane * 8;
#pragma unroll
    for (int ks = 0; ks < 4; ks++) {
        int kg = kg0 + ks;
        u32 bh[4][2], bl[4][2];
#pragma unroll
        for (int nf = 0; nf < 4; nf++) {
            lds64(blh + ks * 4096 + nf * 256, bh[nf][0], bh[nf][1]);
            lds64(bll + ks * 4096 + nf * 256, bl[nf][0], bl[nf][1]);
        }
#pragma unroll
        for (int mg = 0; mg < 2; mg++) {
            u32 ah[2][4], al[2][4];
#pragma unroll
            for (int m = 0; m < 2; m++) {
                int mt = mg * 2 + m;
                lds128(hb + (u32)(((wr * 4 + mt) * 8 + kg) * 512) + lane * 16, ah[m]);
                lds128(hb + (u32)((((2 + wr) * 4 + mt) * 8 + kg) * 512) + lane * 16,
                       al[m]);
            }
#pragma unroll
            for (int m = 0; m < 2; m++)
#pragma unroll
                for (int nf = 0; nf < 4; nf++)
                    mma16816(acc[mg * 2 + m][nf], ah[m], bh[nf][0], bh[nf][1]);
#pragma unroll
            for (int m = 0; m < 2; m++)
#pragma unroll
                for (int nf = 0; nf < 4; nf++)
                    mma16816(acc[mg * 2 + m][nf], ah[m], bl[nf][0], bl[nf][1]);
#pragma unroll
            for (int m = 0; m < 2; m++)
#pragma unroll
                for (int nf = 0; nf < 4; nf++)
                    mma16816(acc[mg * 2 + m][nf], al[m], bh[nf][0], bh[nf][1]);
        }
    }
}

// epilogue: relu(acc + bias) -> hidden fragments; zero acc
__device__ __forceinline__ void epi_hidden(float (*acc)[4][4], const float* bias, u32 hb,
                                           int lane, int wr, int wc) {
    const int c2 = (lane & 3) * 2;
#pragma unroll
    for (int mt = 0; mt < 4; mt++) {
#pragma unroll
        for (int p = 0; p < 2; p++) {
            u32 h[4], l[4];
#pragma unroll
            for (int q = 0; q < 2; q++) {
                int nf = p * 2 + q;
                int n0 = wc * 32 + nf * 8 + c2;
                float v0 = fmaxf(acc[mt][nf][0] + bias[n0], 0.0f);
                float v1 = fmaxf(acc[mt][nf][1] + bias[n0 + 1], 0.0f);
                float v2 = fmaxf(acc[mt][nf][2] + bias[n0], 0.0f);
                float v3 = fmaxf(acc[mt][nf][3] + bias[n0 + 1], 0.0f);
                split2(v0, v1, h[q * 2], l[q * 2]);
                split2(v2, v3, h[q * 2 + 1], l[q * 2 + 1]);
            }
            int kg = wc * 2 + p;
            sts128(hb + (u32)(((wr * 4 + mt) * 8 + kg) * 512) + lane * 16, h);
            sts128(hb + (u32)((((2 + wr) * 4 + mt) * 8 + kg) * 512) + lane * 16, l);
        }
#pragma unroll
        for (int nf = 0; nf < 4; nf++)
#pragma unroll
            for (int j = 0; j < 4; j++) acc[mt][nf][j] = 0.0f;
    }
}

// transpose acc (no bias) into scatter buffer, 528B row stride
__device__ __forceinline__ void acc_to_scat(float (*acc)[4][4], u32 sb, int lane, int wr,
                                            int wc) {
    const int rr = lane >> 2, c2 = (lane & 3) * 2;
#pragma unroll
    for (int mt = 0; mt < 4; mt++) {
        const int r0 = wr * 64 + mt * 16 + rr, r1 = r0 + 8;
#pragma unroll
        for (int nf = 0; nf < 4; nf++) {
            int n0 = wc * 32 + nf * 8 + c2;
            sts64f(sb + (u32)r0 * SCAT_STRIDE + n0 * 4, acc[mt][nf][0], acc[mt][nf][1]);
            sts64f(sb + (u32)r1 * SCAT_STRIDE + n0 * 4, acc[mt][nf][2], acc[mt][nf][3]);
        }
    }
}

// ---------------- kernel 0: weight prep ----------------
__device__ __forceinline__ int fidx(int ke, int n, int split) {
    int chunk = ke >> 6, ks = (ke >> 4) & 3, r = (ke >> 3) & 1, l4 = (ke >> 1) & 3;
    int nf = n >> 3, lane = (n & 7) * 4 + l4;
    return (((chunk * 2 + split) * 4 + ks) * 16 + nf) * 64 + lane * 2 + r;
}

__global__ void prep_weights(const float* __restrict__ W1a, const float* __restrict__ W1b,
                             const float* __restrict__ W2a, const float* __restrict__ W2b) {
    int total = 16384 + 3 * 8192;
    for (int i = blockIdx.x * blockDim.x + threadIdx.x; i < total;
         i += gridDim.x * blockDim.x) {
        int j = i;
        const float* W;
        u32* G;
        if (j < 16384) {
            W = W1a;
            G = g_w1a_f;
        } else {
            j -= 16384;
            int ws = j / 8192;
            j %= 8192;
            W = (ws == 0) ? W1b : (ws == 1) ? W2a : W2b;
            G = (ws == 0) ? g_w1b_f : (ws == 1) ? g_w2a_f : g_w2b_f;
        }
        int ke = (j >> 7) * 2, n = j & 127;
        float x0 = W[ke * 128 + n], x1 = W[(ke + 1) * 128 + n];
        u32 H, L;
        split2(x0, x1, H, L);
        G[fidx(ke, n, 0)] = H;
        G[fidx(ke, n, 1)] = L;
    }
}

// ---------------- kernel 1: g_agg = node_feats ----------------
__global__ void init_agg_kernel(const float* __restrict__ node_feats, int total4) {
    int i = blockIdx.x * blockDim.x + threadIdx.x;
    int stride = gridDim.x * blockDim.x;
    const float4* s = (const float4*)node_feats;
    float4* d = (float4*)g_agg;
    for (; i < total4; i += stride) d[i] = s[i];
}

// ---------------- kernel 2: edge MLP + scatter ----------------
extern __shared__ char dynraw[];

__global__ __launch_bounds__(256, 2) void edge_kernel(
    const float* __restrict__ node_feats, const float* __restrict__ edge_feats,
    const int* __restrict__ src, const int* __restrict__ dst,
    const float* __restrict__ b1a, const float* __restrict__ b1b, int n_edges) {
    __shared__ int s_src[128], s_dst[128];
    __shared__ float s_ba[FEAT], s_bb[FEAT];

    const int tid = threadIdx.x;
    const int wid = tid >> 5, lane = tid & 31;
    const int wr = wid >> 2, wc = wid & 3;
    const u32 smb = smem_u32(dynraw);
    const u32 hb = smb;  // hidden fragments alias A region
    const u32 wb0 = smb + WB0_OFF, wb1 = smb + WB1_OFF;

    const int e0 = blockIdx.x * 128;
    if (tid < 128) {
        int e = min(e0 + tid, n_edges - 1);
        s_src[tid] = __ldg(src + e);
        s_dst[tid] = __ldg(dst + e);
        s_ba[tid] = __ldg(b1a + tid);
        s_bb[tid] = __ldg(b1b + tid);
    }
    __syncthreads();

    float acc[4][4][4];
#pragma unroll
    for (int mt = 0; mt < 4; mt++)
#pragma unroll
        for (int nf = 0; nf < 4; nf++)
#pragma unroll
            for (int j = 0; j < 4; j++) acc[mt][nf][j] = 0.0f;

    const int row = tid & 127, hh = tid >> 7;
    const u32 sstg = smb + STG_OFF + (u32)row * STG_STRIDE + hh * 128;
    const u32 sdst = smb + (u32)row * A_STRIDE + hh * 64;
    const int erow = min(e0 + row, n_edges - 1);
    const u32 aWarp0 = smb + (u32)wr * 64 * A_STRIDE;

    auto rowp = [&](int c) -> const float* {
        if (c < 2) return node_feats + (size_t)s_src[row] * FEAT + c * 64 + hh * 32;
        return edge_feats + (size_t)erow * FEAT + (c - 2) * 64 + hh * 32;
    };

    // ---- prologue: stage A(0) + W(0), convert ----
    stage_row(rowp(0), sstg);
    cp_w16(g_w1a_f, wb0, tid);
    cp_w16(g_w1a_f + 4096, wb1, tid);
    CP_WAIT0();
    convert_own(sstg, sdst);
    __syncthreads();

    // ---- layer 1: K=256, 4 chunks ----
#pragma unroll 1
    for (int c = 0; c < 4; c++) {
        if (c < 3) stage_row(rowp(c + 1), sstg);  // lands during gemm
        g1_fused(aWarp0, wb0, wb1, acc, lane, wc);
        __syncthreads();  // A tile + weights free
        if (c < 3) {
            cp_w16(g_w1a_f + (c + 1) * 8192, wb0, tid);
            cp_w16(g_w1a_f + (c + 1) * 8192 + 4096, wb1, tid);
            CP_WAIT0();
            convert_own(sstg, sdst);
            __syncthreads();
        }
    }

    // ---- epilogue 1: issue layer-2 chunk-0 weights, relu -> hidden fragments ----
    cp_w16(g_w1b_f, wb0, tid);
    cp_w16(g_w1b_f + 4096, wb1, tid);
    epi_hidden(acc, s_ba, hb, lane, wr, wc);
    CP_WAIT0();
    __syncthreads();  // hidden writes + weights visible

    // ---- layer 2: K=128, 2 chunks ----
    g2_fused(hb, wb0, wb1, acc, lane, wr, wc, 0);
    __syncthreads();
    cp_w16(g_w1b_f + 8192, wb0, tid);
    cp_w16(g_w1b_f + 8192 + 4096, wb1, tid);
    CP_WAIT0();
    __syncthreads();
    g2_fused(hb, wb0, wb1, acc, lane, wr, wc, 4);
    __syncthreads();  // hidden region free for scatter buffer

    // ---- epilogue 2: transpose to smem, coalesced vector red into g_agg ----
    acc_to_scat(acc, smb, lane, wr, wc);
    __syncthreads();
    {
        const int l4 = lane * 4;
        const float4 bias = make_float4(s_bb[l4], s_bb[l4 + 1], s_bb[l4 + 2], s_bb[l4 + 3]);
#pragma unroll 1
        for (int q = 0; q < 16; q++) {
            int r = wid * 16 + q;
            if (e0 + r < n_edges) {
                u32 w[4];
                lds128(smb + (u32)r * SCAT_STRIDE + lane * 16, w);
                float* p = g_agg + (size_t)s_dst[r] * FEAT + l4;
                red_v4(p, __uint_as_float(w[0]) + bias.x, __uint_as_float(w[1]) + bias.y,
                       __uint_as_float(w[2]) + bias.z, __uint_as_float(w[3]) + bias.w);
            }
        }
    }
}

// ---------------- kernel 3: node MLP ----------------
__global__ __launch_bounds__(256, 2) void node_kernel(const float* __restrict__ b2a,
                                                      const float* __restrict__ b2b,
                                                      float* __restrict__ out, int n_nodes) {
    __shared__ float s_ba[FEAT], s_bb[FEAT];

    const int tid = threadIdx.x;
    const int wid = tid >> 5, lane = tid & 31;
    const int wr = wid >> 2, wc = wid & 3;
    const u32 smb = smem_u32(dynraw);
    const u32 hb = smb;
    const u32 wb0 = smb + WB0_OFF, wb1 = smb + WB1_OFF;

    const int v0 = blockIdx.x * 128;
    if (tid < 128) {
        s_ba[tid] = __ldg(b2a + tid);
        s_bb[tid] = __ldg(b2b + tid);
    }
    __syncthreads();

    float acc[4][4][4];
#pragma unroll
    for (int mt = 0; mt < 4; mt++)
#pragma unroll
        for (int nf = 0; nf < 4; nf++)
#pragma unroll
            for (int j = 0; j < 4; j++) acc[mt][nf][j] = 0.0f;

    const int row = tid & 127, hh = tid >> 7;
    const u32 sstg = smb + STG_OFF + (u32)row * STG_STRIDE + hh * 128;
    const u32 sdst = smb + (u32)row * A_STRIDE + hh * 64;
    const size_t grow = (size_t)min(v0 + row, n_nodes - 1) * FEAT;
    const u32 aWarp0 = smb + (u32)wr * 64 * A_STRIDE;

    // ---- prologue ----
    stage_row(g_agg + grow + hh * 32, sstg);
    cp_w16(g_w2a_f, wb0, tid);
    cp_w16(g_w2a_f + 4096, wb1, tid);
    CP_WAIT0();
    convert_own(sstg, sdst);
    __syncthreads();

    // ---- layer 1: K=128, 2 chunks ----
#pragma unroll 1
    for (int c = 0; c < 2; c++) {
        if (c < 1) stage_row(g_agg + grow + 64 + hh * 32, sstg);
        g1_fused(aWarp0, wb0, wb1, acc, lane, wc);
        __syncthreads();
        if (c < 1) {
            cp_w16(g_w2a_f + 8192, wb0, tid);
            cp_w16(g_w2a_f + 8192 + 4096, wb1, tid);
            CP_WAIT0();
            convert_own(sstg, sdst);
            __syncthreads();
        }
    }

    // ---- epilogue 1 ----
    cp_w16(g_w2b_f, wb0, tid);
    cp_w16(g_w2b_f + 4096, wb1, tid);
    epi_hidden(acc, s_ba, hb, lane, wr, wc);
    CP_WAIT0();
    __syncthreads();

    // ---- layer 2: K=128, 2 chunks ----
    g2_fused(hb, wb0, wb1, acc, lane, wr, wc, 0);
    __syncthreads();
    cp_w16(g_w2b_f + 8192, wb0, tid);
    cp_w16(g_w2b_f + 8192 + 4096, wb1, tid);
    CP_WAIT0();
    __syncthreads();
    g2_fused(hb, wb0, wb1, acc, lane, wr, wc, 4);
    __syncthreads();

    // ---- epilogue 2: transpose to smem, coalesced STG.128 ----
    acc_to_scat(acc, smb, lane, wr, wc);
    __syncthreads();
    {
        const int l4 = lane * 4;
        const float4 bias = make_float4(s_bb[l4], s_bb[l4 + 1], s_bb[l4 + 2], s_bb[l4 + 3]);
#pragma unroll 1
        for (int q = 0; q < 16; q++) {
            int r = wid * 16 + q;
            if (v0 + r < n_nodes) {
                u32 w[4];
                lds128(smb + (u32)r * SCAT_STRIDE + lane * 16, w);
                float4 v = make_float4(__uint_as_float(w[0]) + bias.x,
                                       __uint_as_float(w[1]) + bias.y,
                                       __uint_as_float(w[2]) + bias.z,
                                       __uint_as_float(w[3]) + bias.w);
                *(float4*)(out + (size_t)(v0 + r) * FEAT + l4) = v;
            }
        }
    }
}

// ---------------- launch ----------------
extern "C" void kernel_launch(void* const* d_in, const int* in_sizes, int n_in,
                              void* d_out, int out_size) {
    const float* node_feats = (const float*)d_in[0];
    const float* edge_feats = (const float*)d_in[1];
    const int* src = (const int*)d_in[2];
    const int* dst = (const int*)d_in[3];
    const float* W1a = (const float*)d_in[4];
    const float* b1a = (const float*)d_in[5];
    const float* W1b = (const float*)d_in[6];
    const float* b1b = (const float*)d_in[7];
    const float* W2a = (const float*)d_in[8];
    const float* b2a = (const float*)d_in[9];
    const float* W2b = (const float*)d_in[10];
    const float* b2b = (const float*)d_in[11];
    float* out = (float*)d_out;

    const int n_nodes = in_sizes[0] / FEAT;
    const int n_edges = in_sizes[2];

    cudaFuncSetAttribute(edge_kernel, cudaFuncAttributeMaxDynamicSharedMemorySize,
                         DYN_BYTES);
    cudaFuncSetAttribute(node_kernel, cudaFuncAttributeMaxDynamicSharedMemorySize,
                         DYN_BYTES);

    prep_weights<<<160, 256>>>(W1a, W1b, W2a, W2b);
    init_agg_kernel<<<512, 256>>>(node_feats, n_nodes * (FEAT / 4));

    int edge_blocks = (n_edges + 127) / 128;
    edge_kernel<<<edge_blocks, 256, DYN_BYTES>>>(node_feats, edge_feats, src, dst, b1a,
                                                 b1b, n_edges);

    int node_blocks = (n_nodes + 127) / 128;
    node_kernel<<<node_blocks, 256, DYN_BYTES>>>(b2a, b2b, out, n_nodes);
}

// round 15
// speedup vs baseline: 1.4836x; 1.4836x over previous
#include <cuda_runtime.h>
#include <cuda_bf16.h>

#define FEAT 128
#define MAX_NODES 50000

typedef unsigned int u32;

// ---------------- device scratch ----------------
static __device__ float g_agg[(size_t)MAX_NODES * FEAT];
// bf16 weight fragments, u32-packed per mma.m16n8k16 B-lane layout:
// idx = (((chunk*2+split)*4 + ks)*16 + nf)*64 + lane*2 + r
static __device__ __align__(16) u32 g_w1a_f[32768];  // K=256: 4 chunks
static __device__ __align__(16) u32 g_w1b_f[16384];  // K=128: 2 chunks
static __device__ __align__(16) u32 g_w2a_f[16384];
static __device__ __align__(16) u32 g_w2b_f[16384];

// ---- smem geometry (dynamic, bytes), M=64 per CTA ----
// A bf16 tile: hi @0 (64 x 144B = 9216), lo @9216          -> 18432
// fp32 stage:  @18432, 64 x 272B = 17408                   -> 35840
// weights:     wb0 @35840 (16KB), wb1 @52224 (16KB)        -> 68608
// hidden fragments (32KB) alias [0..32768) during layer 2.
#define A_STRIDE   144
#define A_TILEB    9216
#define STG_OFF    18432
#define STG_STRIDE 272
#define WB0_OFF    35840
#define WB1_OFF    52224
#define DYN_BYTES  68608

// ---------------- helpers ----------------
__device__ __forceinline__ u32 smem_u32(const void* p) {
    u32 a;
    asm("{ .reg .u64 t; cvta.to.shared.u64 t, %1; cvt.u32.u64 %0, t; }" : "=r"(a) : "l"(p));
    return a;
}
__device__ __forceinline__ u32 lds32(u32 a) {
    u32 v;
    asm volatile("ld.shared.b32 %0, [%1];" : "=r"(v) : "r"(a));
    return v;
}
__device__ __forceinline__ void lds64(u32 a, u32& x, u32& y) {
    asm volatile("ld.shared.v2.b32 {%0,%1}, [%2];" : "=r"(x), "=r"(y) : "r"(a));
}
__device__ __forceinline__ void lds128(u32 a, u32* r) {
    asm volatile("ld.shared.v4.b32 {%0,%1,%2,%3}, [%4];"
                 : "=r"(r[0]), "=r"(r[1]), "=r"(r[2]), "=r"(r[3]) : "r"(a));
}
__device__ __forceinline__ void sts64(u32 a, u32 x, u32 y) {
    asm volatile("st.shared.v2.b32 [%0], {%1,%2};" ::"r"(a), "r"(x), "r"(y));
}
__device__ __forceinline__ void sts128(u32 a, const u32* r) {
    asm volatile("st.shared.v4.b32 [%0], {%1,%2,%3,%4};" ::"r"(a), "r"(r[0]), "r"(r[1]),
                 "r"(r[2]), "r"(r[3]));
}

__device__ __forceinline__ void mma16816(float c[4], const u32 a[4], u32 b0, u32 b1) {
    asm volatile(
        "mma.sync.aligned.m16n8k16.row.col.f32.bf16.bf16.f32 "
        "{%0,%1,%2,%3}, {%4,%5,%6,%7}, {%8,%9}, {%0,%1,%2,%3};"
        : "+f"(c[0]), "+f"(c[1]), "+f"(c[2]), "+f"(c[3])
        : "r"(a[0]), "r"(a[1]), "r"(a[2]), "r"(a[3]), "r"(b0), "r"(b1));
}

// fp32 pair -> packed bf16x2 hi + bf16x2 lo (x in low half)
__device__ __forceinline__ void split2(float x, float y, u32& h, u32& l) {
    asm("cvt.rn.bf16x2.f32 %0, %1, %2;" : "=r"(h) : "f"(y), "f"(x));
    float rx = x - __uint_as_float(h << 16);
    float ry = y - __uint_as_float(h & 0xFFFF0000u);
    asm("cvt.rn.bf16x2.f32 %0, %1, %2;" : "=r"(l) : "f"(ry), "f"(rx));
}

// ---- cp.async staging: each thread stages 16 fp32 (its own convert slice) ----
__device__ __forceinline__ void stage_row(const float* __restrict__ sp, u32 sd) {
#pragma unroll
    for (int q = 0; q < 4; q++) {
        asm volatile("cp.async.cg.shared.global [%0], [%1], 16;" ::"r"(sd + q * 16),
                     "l"(sp + q * 4));
    }
    asm volatile("cp.async.commit_group;");
}

// convert own staged 16 fp32 -> hi/lo bf16 in A tile (smem -> smem)
__device__ __forceinline__ void convert_own(u32 ss, u32 dhi) {
#pragma unroll
    for (int q = 0; q < 4; q++) {
        u32 w[4];
        lds128(ss + q * 16, w);
        u32 h0, l0, h1, l1;
        split2(__uint_as_float(w[0]), __uint_as_float(w[1]), h0, l0);
        split2(__uint_as_float(w[2]), __uint_as_float(w[3]), h1, l1);
        sts64(dhi + q * 8, h0, h1);
        sts64(dhi + A_TILEB + q * 8, l0, l1);
    }
}

// async-copy one 16KB weight split-tile global -> smem (256 threads)
__device__ __forceinline__ void cp_w16(const u32* __restrict__ g, u32 sB, int tid) {
#pragma unroll
    for (int i = 0; i < 4; i++) {
        u32 d = sB + (u32)(tid + i * 256) * 16;
        const u32* s = g + (tid + i * 256) * 4;
        asm volatile("cp.async.cg.shared.global [%0], [%1], 16;" ::"r"(d), "l"(s));
    }
    asm volatile("cp.async.commit_group;");
}
#define CP_WAIT1() asm volatile("cp.async.wait_group 1;" ::: "memory")
#define CP_WAIT0() asm volatile("cp.async.wait_group 0;" ::: "memory")

// ---- fused layer-1 GEMM chunk: warp tile 32x32 (2 mt x 4 nf) ----
// acc += A_hi*B_hi + A_hi*B_lo + A_lo*B_hi, K=64 per chunk.
__device__ __forceinline__ void g1_fused(u32 aHi, u32 wbh, u32 wbl, float (*acc)[4][4],
                                         int lane, int wc) {
    const u32 arow = aHi + (u32)(lane >> 2) * A_STRIDE + (lane & 3) * 4;
    const u32 blh = wbh + (u32)wc * 1024 + lane * 8;
    const u32 bll = wbl + (u32)wc * 1024 + lane * 8;
#pragma unroll
    for (int ks = 0; ks < 4; ks++) {
        u32 bh[4][2], bl[4][2];
#pragma unroll
        for (int nf = 0; nf < 4; nf++) {
            lds64(blh + ks * 4096 + nf * 256, bh[nf][0], bh[nf][1]);
            lds64(bll + ks * 4096 + nf * 256, bl[nf][0], bl[nf][1]);
        }
        u32 ah[2][4], al[2][4];
#pragma unroll
        for (int m = 0; m < 2; m++) {
            u32 ab = arow + m * (16 * A_STRIDE) + ks * 32;
            ah[m][0] = lds32(ab);
            ah[m][1] = lds32(ab + 8 * A_STRIDE);
            ah[m][2] = lds32(ab + 16);
            ah[m][3] = lds32(ab + 8 * A_STRIDE + 16);
            u32 ao = ab + A_TILEB;
            al[m][0] = lds32(ao);
            al[m][1] = lds32(ao + 8 * A_STRIDE);
            al[m][2] = lds32(ao + 16);
            al[m][3] = lds32(ao + 8 * A_STRIDE + 16);
        }
        // 3 passes of 8 independent accumulators
#pragma unroll
        for (int m = 0; m < 2; m++)
#pragma unroll
            for (int nf = 0; nf < 4; nf++)
                mma16816(acc[m][nf], ah[m], bh[nf][0], bh[nf][1]);
#pragma unroll
        for (int m = 0; m < 2; m++)
#pragma unroll
            for (int nf = 0; nf < 4; nf++)
                mma16816(acc[m][nf], ah[m], bl[nf][0], bl[nf][1]);
#pragma unroll
        for (int m = 0; m < 2; m++)
#pragma unroll
            for (int nf = 0; nf < 4; nf++)
                mma16816(acc[m][nf], al[m], bh[nf][0], bh[nf][1]);
    }
}

// ---- fused layer-2 GEMM chunk: A from hidden fragments ----
// slot addr: hb + (((split*2 + wr)*2 + mt)*8 + kg)*512 + lane*16
__device__ __forceinline__ void g2_fused(u32 hb, u32 wbh, u32 wbl, float (*acc)[4][4],
                                         int lane, int wr, int wc, int kg0) {
    const u32 blh = wbh + (u32)wc * 1024 + lane * 8;
    const u32 bll = wbl + (u32)wc * 1024 + lane * 8;
#pragma unroll
    for (int ks = 0; ks < 4; ks++) {
        int kg = kg0 + ks;
        u32 bh[4][2], bl[4][2];
#pragma unroll
        for (int nf = 0; nf < 4; nf++) {
            lds64(blh + ks * 4096 + nf * 256, bh[nf][0], bh[nf][1]);
            lds64(bll + ks * 4096 + nf * 256, bl[nf][0], bl[nf][1]);
        }
        u32 ah[2][4], al[2][4];
#pragma unroll
        for (int m = 0; m < 2; m++) {
            lds128(hb + (u32)((((0 * 2 + wr) * 2 + m) * 8 + kg) * 512) + lane * 16, ah[m]);
            lds128(hb + (u32)((((1 * 2 + wr) * 2 + m) * 8 + kg) * 512) + lane * 16, al[m]);
        }
#pragma unroll
        for (int m = 0; m < 2; m++)
#pragma unroll
            for (int nf = 0; nf < 4; nf++)
                mma16816(acc[m][nf], ah[m], bh[nf][0], bh[nf][1]);
#pragma unroll
        for (int m = 0; m < 2; m++)
#pragma unroll
            for (int nf = 0; nf < 4; nf++)
                mma16816(acc[m][nf], ah[m], bl[nf][0], bl[nf][1]);
#pragma unroll
        for (int m = 0; m < 2; m++)
#pragma unroll
            for (int nf = 0; nf < 4; nf++)
                mma16816(acc[m][nf], al[m], bh[nf][0], bh[nf][1]);
    }
}

// epilogue: relu(acc + bias) -> hidden fragments (direct A-frag layout); zero acc
__device__ __forceinline__ void epi_hidden(float (*acc)[4][4], const float* bias, u32 hb,
                                           int lane, int wr, int wc) {
    const int c2 = (lane & 3) * 2;
#pragma unroll
    for (int mt = 0; mt < 2; mt++) {
#pragma unroll
        for (int p = 0; p < 2; p++) {
            u32 h[4], l[4];
#pragma unroll
            for (int q = 0; q < 2; q++) {
                int nf = p * 2 + q;
                int n0 = wc * 32 + nf * 8 + c2;
                float v0 = fmaxf(acc[mt][nf][0] + bias[n0], 0.0f);
                float v1 = fmaxf(acc[mt][nf][1] + bias[n0 + 1], 0.0f);
                float v2 = fmaxf(acc[mt][nf][2] + bias[n0], 0.0f);
                float v3 = fmaxf(acc[mt][nf][3] + bias[n0 + 1], 0.0f);
                split2(v0, v1, h[q * 2], l[q * 2]);
                split2(v2, v3, h[q * 2 + 1], l[q * 2 + 1]);
            }
            int kg = wc * 2 + p;
            sts128(hb + (u32)((((0 * 2 + wr) * 2 + mt) * 8 + kg) * 512) + lane * 16, h);
            sts128(hb + (u32)((((1 * 2 + wr) * 2 + mt) * 8 + kg) * 512) + lane * 16, l);
        }
#pragma unroll
        for (int nf = 0; nf < 4; nf++)
#pragma unroll
            for (int j = 0; j < 4; j++) acc[mt][nf][j] = 0.0f;
    }
}

// ---------------- kernel 0: weight prep (split + fragment pack) ----------------
__device__ __forceinline__ int fidx(int ke, int n, int split) {
    int chunk = ke >> 6, ks = (ke >> 4) & 3, r = (ke >> 3) & 1, l4 = (ke >> 1) & 3;
    int nf = n >> 3, lane = (n & 7) * 4 + l4;
    return (((chunk * 2 + split) * 4 + ks) * 16 + nf) * 64 + lane * 2 + r;
}

__global__ void prep_weights(const float* __restrict__ W1a, const float* __restrict__ W1b,
                             const float* __restrict__ W2a, const float* __restrict__ W2b) {
    int total = 16384 + 3 * 8192;
    for (int i = blockIdx.x * blockDim.x + threadIdx.x; i < total;
         i += gridDim.x * blockDim.x) {
        int j = i;
        const float* W;
        u32* G;
        if (j < 16384) {
            W = W1a;
            G = g_w1a_f;
        } else {
            j -= 16384;
            int ws = j / 8192;
            j %= 8192;
            W = (ws == 0) ? W1b : (ws == 1) ? W2a : W2b;
            G = (ws == 0) ? g_w1b_f : (ws == 1) ? g_w2a_f : g_w2b_f;
        }
        int ke = (j >> 7) * 2, n = j & 127;
        float x0 = W[ke * 128 + n], x1 = W[(ke + 1) * 128 + n];
        u32 H, L;
        split2(x0, x1, H, L);
        G[fidx(ke, n, 0)] = H;
        G[fidx(ke, n, 1)] = L;
    }
}

// ---------------- kernel 1: g_agg = node_feats ----------------
__global__ void init_agg_kernel(const float* __restrict__ node_feats, int total4) {
    int i = blockIdx.x * blockDim.x + threadIdx.x;
    int stride = gridDim.x * blockDim.x;
    const float4* s = (const float4*)node_feats;
    float4* d = (float4*)g_agg;
    for (; i < total4; i += stride) d[i] = s[i];
}

// ---------------- kernel 2: edge MLP + scatter (M=64 per CTA) ----------------
extern __shared__ char dynraw[];

__global__ __launch_bounds__(256, 3) void edge_kernel(
    const float* __restrict__ node_feats, const float* __restrict__ edge_feats,
    const int* __restrict__ src, const int* __restrict__ dst,
    const float* __restrict__ b1a, const float* __restrict__ b1b, int n_edges) {
    __shared__ int s_src[64], s_dst[64];
    __shared__ float s_ba[FEAT], s_bb[FEAT];

    const int tid = threadIdx.x;
    const int wid = tid >> 5, lane = tid & 31;
    const int wr = wid >> 2, wc = wid & 3;
    const u32 smb = smem_u32(dynraw);
    const u32 hb = smb;  // hidden fragments alias A region
    const u32 wb0 = smb + WB0_OFF, wb1 = smb + WB1_OFF;

    const int e0 = blockIdx.x * 64;
    if (tid < 64) {
        int e = min(e0 + tid, n_edges - 1);
        s_src[tid] = __ldg(src + e);
        s_dst[tid] = __ldg(dst + e);
    }
    if (tid >= 128) {
        s_ba[tid - 128] = __ldg(b1a + tid - 128);
        s_bb[tid - 128] = __ldg(b1b + tid - 128);
    }
    __syncthreads();

    float acc[2][4][4];
#pragma unroll
    for (int mt = 0; mt < 2; mt++)
#pragma unroll
        for (int nf = 0; nf < 4; nf++)
#pragma unroll
            for (int j = 0; j < 4; j++) acc[mt][nf][j] = 0.0f;

    const int row = tid >> 2, hh = tid & 3;  // own slice: 16 floats
    const u32 sstg = smb + STG_OFF + (u32)row * STG_STRIDE + hh * 64;
    const u32 sdst = smb + (u32)row * A_STRIDE + hh * 32;
    const int erow = min(e0 + row, n_edges - 1);
    const u32 aWarp = smb + (u32)wr * 32 * A_STRIDE;

    auto rowp = [&](int c) -> const float* {
        if (c < 2) return node_feats + (size_t)s_src[row] * FEAT + c * 64 + hh * 16;
        return edge_feats + (size_t)erow * FEAT + (c - 2) * 64 + hh * 16;
    };

    // ---- prologue: stage A(0) + W(0), convert ----
    stage_row(rowp(0), sstg);
    cp_w16(g_w1a_f, wb0, tid);
    cp_w16(g_w1a_f + 4096, wb1, tid);
    CP_WAIT0();
    convert_own(sstg, sdst);
    __syncthreads();

    // ---- layer 1: K=256, 4 chunks ----
#pragma unroll 1
    for (int c = 0; c < 4; c++) {
        if (c < 3) stage_row(rowp(c + 1), sstg);  // lands during gemm
        g1_fused(aWarp, wb0, wb1, acc, lane, wc);
        __syncthreads();  // A tile + weights + stage free
        if (c < 3) {
            cp_w16(g_w1a_f + (c + 1) * 8192, wb0, tid);
            cp_w16(g_w1a_f + (c + 1) * 8192 + 4096, wb1, tid);
            CP_WAIT0();
            convert_own(sstg, sdst);
            __syncthreads();
        }
    }

    // ---- epilogue 1: issue layer-2 chunk-0 weights; relu -> hidden fragments ----
    cp_w16(g_w1b_f, wb0, tid);
    cp_w16(g_w1b_f + 4096, wb1, tid);
    epi_hidden(acc, s_ba, hb, lane, wr, wc);
    CP_WAIT0();
    __syncthreads();

    // ---- layer 2: K=128, 2 chunks ----
    g2_fused(hb, wb0, wb1, acc, lane, wr, wc, 0);
    __syncthreads();
    cp_w16(g_w1b_f + 8192, wb0, tid);
    cp_w16(g_w1b_f + 8192 + 4096, wb1, tid);
    CP_WAIT0();
    __syncthreads();
    g2_fused(hb, wb0, wb1, acc, lane, wr, wc, 4);

    // ---- epilogue 2: scatter (acc + b1b) into g_agg ----
    const int rr = lane >> 2, c2 = (lane & 3) * 2;
#pragma unroll
    for (int mt = 0; mt < 2; mt++) {
        const int r0 = wr * 32 + mt * 16 + rr, r1 = r0 + 8;
        float* p0 = g_agg + (size_t)s_dst[r0] * FEAT;
        float* p1 = g_agg + (size_t)s_dst[r1] * FEAT;
        const bool ok0 = (e0 + r0 < n_edges), ok1 = (e0 + r1 < n_edges);
#pragma unroll
        for (int nf = 0; nf < 4; nf++) {
            int n0 = wc * 32 + nf * 8 + c2;
            if (ok0) {
                atomicAdd(p0 + n0, acc[mt][nf][0] + s_bb[n0]);
                atomicAdd(p0 + n0 + 1, acc[mt][nf][1] + s_bb[n0 + 1]);
            }
            if (ok1) {
                atomicAdd(p1 + n0, acc[mt][nf][2] + s_bb[n0]);
                atomicAdd(p1 + n0 + 1, acc[mt][nf][3] + s_bb[n0 + 1]);
            }
        }
    }
}

// ---------------- kernel 3: node MLP (M=64 per CTA) ----------------
__global__ __launch_bounds__(256, 3) void node_kernel(const float* __restrict__ b2a,
                                                      const float* __restrict__ b2b,
                                                      float* __restrict__ out, int n_nodes) {
    __shared__ float s_ba[FEAT], s_bb[FEAT];

    const int tid = threadIdx.x;
    const int wid = tid >> 5, lane = tid & 31;
    const int wr = wid >> 2, wc = wid & 3;
    const u32 smb = smem_u32(dynraw);
    const u32 hb = smb;
    const u32 wb0 = smb + WB0_OFF, wb1 = smb + WB1_OFF;

    const int v0 = blockIdx.x * 64;
    if (tid < 128) {
        s_ba[tid] = __ldg(b2a + tid);
        s_bb[tid] = __ldg(b2b + tid);
    }
    __syncthreads();

    float acc[2][4][4];
#pragma unroll
    for (int mt = 0; mt < 2; mt++)
#pragma unroll
        for (int nf = 0; nf < 4; nf++)
#pragma unroll
            for (int j = 0; j < 4; j++) acc[mt][nf][j] = 0.0f;

    const int row = tid >> 2, hh = tid & 3;
    const u32 sstg = smb + STG_OFF + (u32)row * STG_STRIDE + hh * 64;
    const u32 sdst = smb + (u32)row * A_STRIDE + hh * 32;
    const size_t grow = (size_t)min(v0 + row, n_nodes - 1) * FEAT;
    const u32 aWarp = smb + (u32)wr * 32 * A_STRIDE;

    // ---- prologue ----
    stage_row(g_agg + grow + hh * 16, sstg);
    cp_w16(g_w2a_f, wb0, tid);
    cp_w16(g_w2a_f + 4096, wb1, tid);
    CP_WAIT0();
    convert_own(sstg, sdst);
    __syncthreads();

    // ---- layer 1: K=128, 2 chunks ----
#pragma unroll 1
    for (int c = 0; c < 2; c++) {
        if (c < 1) stage_row(g_agg + grow + 64 + hh * 16, sstg);
        g1_fused(aWarp, wb0, wb1, acc, lane, wc);
        __syncthreads();
        if (c < 1) {
            cp_w16(g_w2a_f + 8192, wb0, tid);
            cp_w16(g_w2a_f + 8192 + 4096, wb1, tid);
            CP_WAIT0();
            convert_own(sstg, sdst);
            __syncthreads();
        }
    }

    // ---- epilogue 1 ----
    cp_w16(g_w2b_f, wb0, tid);
    cp_w16(g_w2b_f + 4096, wb1, tid);
    epi_hidden(acc, s_ba, hb, lane, wr, wc);
    CP_WAIT0();
    __syncthreads();

    // ---- layer 2: K=128, 2 chunks ----
    g2_fused(hb, wb0, wb1, acc, lane, wr, wc, 0);
    __syncthreads();
    cp_w16(g_w2b_f + 8192, wb0, tid);
    cp_w16(g_w2b_f + 8192 + 4096, wb1, tid);
    CP_WAIT0();
    __syncthreads();
    g2_fused(hb, wb0, wb1, acc, lane, wr, wc, 4);

    // ---- epilogue 2: out = acc + b2b ----
    const int rr = lane >> 2, c2 = (lane & 3) * 2;
#pragma unroll
    for (int mt = 0; mt < 2; mt++) {
        const int r0 = wr * 32 + mt * 16 + rr, r1 = r0 + 8;
#pragma unroll
        for (int nf = 0; nf < 4; nf++) {
            int n0 = wc * 32 + nf * 8 + c2;
            if (v0 + r0 < n_nodes) {
                float2 v = make_float2(acc[mt][nf][0] + s_bb[n0],
                                       acc[mt][nf][1] + s_bb[n0 + 1]);
                *(float2*)(out + (size_t)(v0 + r0) * FEAT + n0) = v;
            }
            if (v0 + r1 < n_nodes) {
                float2 v = make_float2(acc[mt][nf][2] + s_bb[n0],
                                       acc[mt][nf][3] + s_bb[n0 + 1]);
                *(float2*)(out + (size_t)(v0 + r1) * FEAT + n0) = v;
            }
        }
    }
}

// ---------------- launch ----------------
extern "C" void kernel_launch(void* const* d_in, const int* in_sizes, int n_in,
                              void* d_out, int out_size) {
    const float* node_feats = (const float*)d_in[0];
    const float* edge_feats = (const float*)d_in[1];
    const int* src = (const int*)d_in[2];
    const int* dst = (const int*)d_in[3];
    const float* W1a = (const float*)d_in[4];
    const float* b1a = (const float*)d_in[5];
    const float* W1b = (const float*)d_in[6];
    const float* b1b = (const float*)d_in[7];
    const float* W2a = (const float*)d_in[8];
    const float* b2a = (const float*)d_in[9];
    const float* W2b = (const float*)d_in[10];
    const float* b2b = (const float*)d_in[11];
    float* out = (float*)d_out;

    const int n_nodes = in_sizes[0] / FEAT;
    const int n_edges = in_sizes[2];

    cudaFuncSetAttribute(edge_kernel, cudaFuncAttributeMaxDynamicSharedMemorySize,
                         DYN_BYTES);
    cudaFuncSetAttribute(node_kernel, cudaFuncAttributeMaxDynamicSharedMemorySize,
                         DYN_BYTES);

    prep_weights<<<160, 256>>>(W1a, W1b, W2a, W2b);
    init_agg_kernel<<<512, 256>>>(node_feats, n_nodes * (FEAT / 4));

    int edge_blocks = (n_edges + 63) / 64;
    edge_kernel<<<edge_blocks, 256, DYN_BYTES>>>(node_feats, edge_feats, src, dst, b1a,
                                                 b1b, n_edges);

    int node_blocks = (n_nodes + 63) / 64;
    node_kernel<<<node_blocks, 256, DYN_BYTES>>>(b2a, b2b, out, n_nodes);
}

// round 16
// speedup vs baseline: 1.5585x; 1.0505x over previous
#include <cuda_runtime.h>
#include <cuda_bf16.h>

#define FEAT 128
#define MAX_NODES 50000

typedef unsigned int u32;

// ---------------- device scratch ----------------
static __device__ float g_agg[(size_t)MAX_NODES * FEAT];
// bf16 weight fragments, hi/lo interleaved per 16B:
// byte = chunk*32768 + ((ks*16 + nf)*32 + lane)*16 + split*8 + r*4
static __device__ __align__(16) u32 g_w1a_f[32768];  // K=256: 4 chunks
static __device__ __align__(16) u32 g_w1b_f[16384];  // K=128: 2 chunks
static __device__ __align__(16) u32 g_w2a_f[16384];
static __device__ __align__(16) u32 g_w2b_f[16384];

// ---- smem geometry (dynamic, bytes), M=64 per CTA ----
// A bf16 tile: hi @0 (64 x 144B = 9216), lo @9216          -> 18432
// fp32 stage:  @18432, 64 x 272B = 17408                   -> 35840
// weights:     wb @35840 (32KB, one K=64 chunk, interleaved)-> 68608
// hidden fragments (32KB) alias [0..32768) during layer 2.
#define A_STRIDE   144
#define A_TILEB    9216
#define STG_OFF    18432
#define STG_STRIDE 272
#define WB_OFF     35840
#define DYN_BYTES  68608

// ---------------- helpers ----------------
__device__ __forceinline__ u32 smem_u32(const void* p) {
    u32 a;
    asm("{ .reg .u64 t; cvta.to.shared.u64 t, %1; cvt.u32.u64 %0, t; }" : "=r"(a) : "l"(p));
    return a;
}
__device__ __forceinline__ void lds128(u32 a, u32* r) {
    asm volatile("ld.shared.v4.b32 {%0,%1,%2,%3}, [%4];"
                 : "=r"(r[0]), "=r"(r[1]), "=r"(r[2]), "=r"(r[3]) : "r"(a));
}
__device__ __forceinline__ void sts64(u32 a, u32 x, u32 y) {
    asm volatile("st.shared.v2.b32 [%0], {%1,%2};" ::"r"(a), "r"(x), "r"(y));
}
__device__ __forceinline__ void sts128(u32 a, const u32* r) {
    asm volatile("st.shared.v4.b32 [%0], {%1,%2,%3,%4};" ::"r"(a), "r"(r[0]), "r"(r[1]),
                 "r"(r[2]), "r"(r[3]));
}
// ldmatrix x4: A m16k16 fragment from row-major bf16 tile
__device__ __forceinline__ void ldmA(u32 a, u32* r) {
    asm volatile("ldmatrix.sync.aligned.m8n8.x4.shared.b16 {%0,%1,%2,%3}, [%4];"
                 : "=r"(r[0]), "=r"(r[1]), "=r"(r[2]), "=r"(r[3]) : "r"(a));
}

__device__ __forceinline__ void mma16816(float c[4], const u32 a[4], u32 b0, u32 b1) {
    asm volatile(
        "mma.sync.aligned.m16n8k16.row.col.f32.bf16.bf16.f32 "
        "{%0,%1,%2,%3}, {%4,%5,%6,%7}, {%8,%9}, {%0,%1,%2,%3};"
        : "+f"(c[0]), "+f"(c[1]), "+f"(c[2]), "+f"(c[3])
        : "r"(a[0]), "r"(a[1]), "r"(a[2]), "r"(a[3]), "r"(b0), "r"(b1));
}

// fp32 pair -> packed bf16x2 hi + bf16x2 lo (x in low half)
__device__ __forceinline__ void split2(float x, float y, u32& h, u32& l) {
    asm("cvt.rn.bf16x2.f32 %0, %1, %2;" : "=r"(h) : "f"(y), "f"(x));
    float rx = x - __uint_as_float(h << 16);
    float ry = y - __uint_as_float(h & 0xFFFF0000u);
    asm("cvt.rn.bf16x2.f32 %0, %1, %2;" : "=r"(l) : "f"(ry), "f"(rx));
}

// ---- cp.async staging: each thread stages 16 fp32 (its own convert slice) ----
__device__ __forceinline__ void stage_row(const float* __restrict__ sp, u32 sd) {
#pragma unroll
    for (int q = 0; q < 4; q++) {
        asm volatile("cp.async.cg.shared.global [%0], [%1], 16;" ::"r"(sd + q * 16),
                     "l"(sp + q * 4));
    }
    asm volatile("cp.async.commit_group;");
}

// convert own staged 16 fp32 -> hi/lo bf16 in A tile (smem -> smem)
__device__ __forceinline__ void convert_own(u32 ss, u32 dhi) {
#pragma unroll
    for (int q = 0; q < 4; q++) {
        u32 w[4];
        lds128(ss + q * 16, w);
        u32 h0, l0, h1, l1;
        split2(__uint_as_float(w[0]), __uint_as_float(w[1]), h0, l0);
        split2(__uint_as_float(w[2]), __uint_as_float(w[3]), h1, l1);
        sts64(dhi + q * 8, h0, h1);
        sts64(dhi + A_TILEB + q * 8, l0, l1);
    }
}

// async-copy one 32KB interleaved weight chunk global -> smem (256 threads)
__device__ __forceinline__ void cp_w32(const u32* __restrict__ g, u32 sB, int tid) {
#pragma unroll
    for (int i = 0; i < 8; i++) {
        u32 d = sB + (u32)(tid + i * 256) * 16;
        const u32* s = g + (tid + i * 256) * 4;
        asm volatile("cp.async.cg.shared.global [%0], [%1], 16;" ::"r"(d), "l"(s));
    }
    asm volatile("cp.async.commit_group;");
}
#define CP_WAIT0() asm volatile("cp.async.wait_group 0;" ::: "memory")

// ---- fused layer-1 GEMM chunk: warp tile 32x32 (2 mt x 4 nf) ----
// acc += A_hi*B_hi + A_hi*B_lo + A_lo*B_hi, K=64 per chunk.
// A via ldmatrix.x4; B hi/lo interleaved, one lds128 per nf.
__device__ __forceinline__ void g1_fused(u32 aHi, u32 wb, float (*acc)[4][4], int lane,
                                         int wc) {
    const u32 arow = aHi + (u32)(lane & 15) * A_STRIDE + (lane >> 4) * 16;
    const u32 bl = wb + (u32)wc * 2048 + lane * 16;  // 4 nf x 512B per warp
#pragma unroll
    for (int ks = 0; ks < 4; ks++) {
        u32 b[4][4];
#pragma unroll
        for (int nf = 0; nf < 4; nf++) lds128(bl + ks * 8192 + nf * 512, b[nf]);
        u32 ah[2][4], al[2][4];
#pragma unroll
        for (int m = 0; m < 2; m++) {
            u32 ab = arow + (u32)(m * 16) * A_STRIDE + ks * 32;
            ldmA(ab, ah[m]);
            ldmA(ab + A_TILEB, al[m]);
        }
        // 3 passes of 8 independent accumulators
#pragma unroll
        for (int m = 0; m < 2; m++)
#pragma unroll
            for (int nf = 0; nf < 4; nf++)
                mma16816(acc[m][nf], ah[m], b[nf][0], b[nf][1]);
#pragma unroll
        for (int m = 0; m < 2; m++)
#pragma unroll
            for (int nf = 0; nf < 4; nf++)
                mma16816(acc[m][nf], ah[m], b[nf][2], b[nf][3]);
#pragma unroll
        for (int m = 0; m < 2; m++)
#pragma unroll
            for (int nf = 0; nf < 4; nf++)
                mma16816(acc[m][nf], al[m], b[nf][0], b[nf][1]);
    }
}

// ---- fused layer-2 GEMM chunk: A from hidden fragments ----
// slot addr: hb + (((split*2 + wr)*2 + mt)*8 + kg)*512 + lane*16
__device__ __forceinline__ void g2_fused(u32 hb, u32 wb, float (*acc)[4][4], int lane,
                                         int wr, int wc, int kg0) {
    const u32 bl = wb + (u32)wc * 2048 + lane * 16;
#pragma unroll
    for (int ks = 0; ks < 4; ks++) {
        int kg = kg0 + ks;
        u32 b[4][4];
#pragma unroll
        for (int nf = 0; nf < 4; nf++) lds128(bl + ks * 8192 + nf * 512, b[nf]);
        u32 ah[2][4], al[2][4];
#pragma unroll
        for (int m = 0; m < 2; m++) {
            lds128(hb + (u32)((((0 * 2 + wr) * 2 + m) * 8 + kg) * 512) + lane * 16, ah[m]);
            lds128(hb + (u32)((((1 * 2 + wr) * 2 + m) * 8 + kg) * 512) + lane * 16, al[m]);
        }
#pragma unroll
        for (int m = 0; m < 2; m++)
#pragma unroll
            for (int nf = 0; nf < 4; nf++)
                mma16816(acc[m][nf], ah[m], b[nf][0], b[nf][1]);
#pragma unroll
        for (int m = 0; m < 2; m++)
#pragma unroll
            for (int nf = 0; nf < 4; nf++)
                mma16816(acc[m][nf], ah[m], b[nf][2], b[nf][3]);
#pragma unroll
        for (int m = 0; m < 2; m++)
#pragma unroll
            for (int nf = 0; nf < 4; nf++)
                mma16816(acc[m][nf], al[m], b[nf][0], b[nf][1]);
    }
}

// epilogue: relu(acc + bias) -> hidden fragments (direct A-frag layout); zero acc
__device__ __forceinline__ void epi_hidden(float (*acc)[4][4], const float* bias, u32 hb,
                                           int lane, int wr, int wc) {
    const int c2 = (lane & 3) * 2;
#pragma unroll
    for (int mt = 0; mt < 2; mt++) {
#pragma unroll
        for (int p = 0; p < 2; p++) {
            u32 h[4], l[4];
#pragma unroll
            for (int q = 0; q < 2; q++) {
                int nf = p * 2 + q;
                int n0 = wc * 32 + nf * 8 + c2;
                float v0 = fmaxf(acc[mt][nf][0] + bias[n0], 0.0f);
                float v1 = fmaxf(acc[mt][nf][1] + bias[n0 + 1], 0.0f);
                float v2 = fmaxf(acc[mt][nf][2] + bias[n0], 0.0f);
                float v3 = fmaxf(acc[mt][nf][3] + bias[n0 + 1], 0.0f);
                split2(v0, v1, h[q * 2], l[q * 2]);
                split2(v2, v3, h[q * 2 + 1], l[q * 2 + 1]);
            }
            int kg = wc * 2 + p;
            sts128(hb + (u32)((((0 * 2 + wr) * 2 + mt) * 8 + kg) * 512) + lane * 16, h);
            sts128(hb + (u32)((((1 * 2 + wr) * 2 + mt) * 8 + kg) * 512) + lane * 16, l);
        }
#pragma unroll
        for (int nf = 0; nf < 4; nf++)
#pragma unroll
            for (int j = 0; j < 4; j++) acc[mt][nf][j] = 0.0f;
    }
}

// ---------------- kernel 0: weight prep (split + interleaved fragment pack) ----
__global__ void prep_weights(const float* __restrict__ W1a, const float* __restrict__ W1b,
                             const float* __restrict__ W2a, const float* __restrict__ W2b) {
    int total = 16384 + 3 * 8192;  // k-pair x n counts
    for (int i = blockIdx.x * blockDim.x + threadIdx.x; i < total;
         i += gridDim.x * blockDim.x) {
        int j = i;
        const float* W;
        u32* G;
        if (j < 16384) {
            W = W1a;
            G = g_w1a_f;
        } else {
            j -= 16384;
            int ws = j / 8192;
            j %= 8192;
            W = (ws == 0) ? W1b : (ws == 1) ? W2a : W2b;
            G = (ws == 0) ? g_w1b_f : (ws == 1) ? g_w2a_f : g_w2b_f;
        }
        int ke = (j >> 7) * 2, n = j & 127;
        float x0 = W[ke * 128 + n], x1 = W[(ke + 1) * 128 + n];
        u32 H, L;
        split2(x0, x1, H, L);
        int chunk = ke >> 6, ks = (ke >> 4) & 3, r = (ke >> 3) & 1, l4 = (ke >> 1) & 3;
        int nf = n >> 3, lane = (n & 7) * 4 + l4;
        // u32 index: chunk*8192 + ((ks*16 + nf)*32 + lane)*4 + split*2 + r
        int base = chunk * 8192 + ((ks * 16 + nf) * 32 + lane) * 4 + r;
        G[base] = H;
        G[base + 2] = L;
    }
}

// ---------------- kernel 1: g_agg = node_feats ----------------
__global__ void init_agg_kernel(const float* __restrict__ node_feats, int total4) {
    int i = blockIdx.x * blockDim.x + threadIdx.x;
    int stride = gridDim.x * blockDim.x;
    const float4* s = (const float4*)node_feats;
    float4* d = (float4*)g_agg;
    for (; i < total4; i += stride) d[i] = s[i];
}

// ---------------- kernel 2: edge MLP + scatter (M=64 per CTA) ----------------
extern __shared__ char dynraw[];

__global__ __launch_bounds__(256, 3) void edge_kernel(
    const float* __restrict__ node_feats, const float* __restrict__ edge_feats,
    const int* __restrict__ src, const int* __restrict__ dst,
    const float* __restrict__ b1a, const float* __restrict__ b1b, int n_edges) {
    __shared__ int s_src[64], s_dst[64];
    __shared__ float s_ba[FEAT], s_bb[FEAT];

    const int tid = threadIdx.x;
    const int wid = tid >> 5, lane = tid & 31;
    const int wr = wid >> 2, wc = wid & 3;
    const u32 smb = smem_u32(dynraw);
    const u32 hb = smb;  // hidden fragments alias A region
    const u32 wb = smb + WB_OFF;

    const int e0 = blockIdx.x * 64;
    if (tid < 64) {
        int e = min(e0 + tid, n_edges - 1);
        s_src[tid] = __ldg(src + e);
        s_dst[tid] = __ldg(dst + e);
    }
    if (tid >= 128) {
        s_ba[tid - 128] = __ldg(b1a + tid - 128);
        s_bb[tid - 128] = __ldg(b1b + tid - 128);
    }
    __syncthreads();

    float acc[2][4][4];
#pragma unroll
    for (int mt = 0; mt < 2; mt++)
#pragma unroll
        for (int nf = 0; nf < 4; nf++)
#pragma unroll
            for (int j = 0; j < 4; j++) acc[mt][nf][j] = 0.0f;

    const int row = tid >> 2, hh = tid & 3;  // own slice: 16 floats
    const u32 sstg = smb + STG_OFF + (u32)row * STG_STRIDE + hh * 64;
    const u32 sdst = smb + (u32)row * A_STRIDE + hh * 32;
    const int erow = min(e0 + row, n_edges - 1);
    const u32 aWarp = smb + (u32)wr * 32 * A_STRIDE;

    auto rowp = [&](int c) -> const float* {
        if (c < 2) return node_feats + (size_t)s_src[row] * FEAT + c * 64 + hh * 16;
        return edge_feats + (size_t)erow * FEAT + (c - 2) * 64 + hh * 16;
    };

    // ---- prologue: stage A(0) + W(0), convert ----
    stage_row(rowp(0), sstg);
    cp_w32(g_w1a_f, wb, tid);
    CP_WAIT0();
    convert_own(sstg, sdst);
    __syncthreads();

    // ---- layer 1: K=256, 4 chunks ----
#pragma unroll 1
    for (int c = 0; c < 4; c++) {
        if (c < 3) stage_row(rowp(c + 1), sstg);  // lands during gemm
        g1_fused(aWarp, wb, acc, lane, wc);
        __syncthreads();  // A tile + weights + stage free
        if (c < 3) {
            cp_w32(g_w1a_f + (c + 1) * 8192, wb, tid);
            CP_WAIT0();
            convert_own(sstg, sdst);
            __syncthreads();
        }
    }

    // ---- epilogue 1: issue layer-2 chunk-0 weights; relu -> hidden fragments ----
    cp_w32(g_w1b_f, wb, tid);
    epi_hidden(acc, s_ba, hb, lane, wr, wc);
    CP_WAIT0();
    __syncthreads();

    // ---- layer 2: K=128, 2 chunks ----
    g2_fused(hb, wb, acc, lane, wr, wc, 0);
    __syncthreads();
    cp_w32(g_w1b_f + 8192, wb, tid);
    CP_WAIT0();
    __syncthreads();
    g2_fused(hb, wb, acc, lane, wr, wc, 4);

    // ---- epilogue 2: scatter (acc + b1b) into g_agg ----
    const int rr = lane >> 2, c2 = (lane & 3) * 2;
#pragma unroll
    for (int mt = 0; mt < 2; mt++) {
        const int r0 = wr * 32 + mt * 16 + rr, r1 = r0 + 8;
        float* p0 = g_agg + (size_t)s_dst[r0] * FEAT;
        float* p1 = g_agg + (size_t)s_dst[r1] * FEAT;
        const bool ok0 = (e0 + r0 < n_edges), ok1 = (e0 + r1 < n_edges);
#pragma unroll
        for (int nf = 0; nf < 4; nf++) {
            int n0 = wc * 32 + nf * 8 + c2;
            if (ok0) {
                atomicAdd(p0 + n0, acc[mt][nf][0] + s_bb[n0]);
                atomicAdd(p0 + n0 + 1, acc[mt][nf][1] + s_bb[n0 + 1]);
            }
            if (ok1) {
                atomicAdd(p1 + n0, acc[mt][nf][2] + s_bb[n0]);
                atomicAdd(p1 + n0 + 1, acc[mt][nf][3] + s_bb[n0 + 1]);
            }
        }
    }
}

// ---------------- kernel 3: node MLP (M=64 per CTA) ----------------
__global__ __launch_bounds__(256, 3) void node_kernel(const float* __restrict__ b2a,
                                                      const float* __restrict__ b2b,
                                                      float* __restrict__ out, int n_nodes) {
    __shared__ float s_ba[FEAT], s_bb[FEAT];

    const int tid = threadIdx.x;
    const int wid = tid >> 5, lane = tid & 31;
    const int wr = wid >> 2, wc = wid & 3;
    const u32 smb = smem_u32(dynraw);
    const u32 hb = smb;
    const u32 wb = smb + WB_OFF;

    const int v0 = blockIdx.x * 64;
    if (tid < 128) {
        s_ba[tid] = __ldg(b2a + tid);
        s_bb[tid] = __ldg(b2b + tid);
    }
    __syncthreads();

    float acc[2][4][4];
#pragma unroll
    for (int mt = 0; mt < 2; mt++)
#pragma unroll
        for (int nf = 0; nf < 4; nf++)
#pragma unroll
            for (int j = 0; j < 4; j++) acc[mt][nf][j] = 0.0f;

    const int row = tid >> 2, hh = tid & 3;
    const u32 sstg = smb + STG_OFF + (u32)row * STG_STRIDE + hh * 64;
    const u32 sdst = smb + (u32)row * A_STRIDE + hh * 32;
    const size_t grow = (size_t)min(v0 + row, n_nodes - 1) * FEAT;
    const u32 aWarp = smb + (u32)wr * 32 * A_STRIDE;

    // ---- prologue ----
    stage_row(g_agg + grow + hh * 16, sstg);
    cp_w32(g_w2a_f, wb, tid);
    CP_WAIT0();
    convert_own(sstg, sdst);
    __syncthreads();

    // ---- layer 1: K=128, 2 chunks ----
#pragma unroll 1
    for (int c = 0; c < 2; c++) {
        if (c < 1) stage_row(g_agg + grow + 64 + hh * 16, sstg);
        g1_fused(aWarp, wb, acc, lane, wc);
        __syncthreads();
        if (c < 1) {
            cp_w32(g_w2a_f + 8192, wb, tid);
            CP_WAIT0();
            convert_own(sstg, sdst);
            __syncthreads();
        }
    }

    // ---- epilogue 1 ----
    cp_w32(g_w2b_f, wb, tid);
    epi_hidden(acc, s_ba, hb, lane, wr, wc);
    CP_WAIT0();
    __syncthreads();

    // ---- layer 2: K=128, 2 chunks ----
    g2_fused(hb, wb, acc, lane, wr, wc, 0);
    __syncthreads();
    cp_w32(g_w2b_f + 8192, wb, tid);
    CP_WAIT0();
    __syncthreads();
    g2_fused(hb, wb, acc, lane, wr, wc, 4);

    // ---- epilogue 2: out = acc + b2b ----
    const int rr = lane >> 2, c2 = (lane & 3) * 2;
#pragma unroll
    for (int mt = 0; mt < 2; mt++) {
        const int r0 = wr * 32 + mt * 16 + rr, r1 = r0 + 8;
#pragma unroll
        for (int nf = 0; nf < 4; nf++) {
            int n0 = wc * 32 + nf * 8 + c2;
            if (v0 + r0 < n_nodes) {
                float2 v = make_float2(acc[mt][nf][0] + s_bb[n0],
                                       acc[mt][nf][1] + s_bb[n0 + 1]);
                *(float2*)(out + (size_t)(v0 + r0) * FEAT + n0) = v;
            }
            if (v0 + r1 < n_nodes) {
                float2 v = make_float2(acc[mt][nf][2] + s_bb[n0],
                                       acc[mt][nf][3] + s_bb[n0 + 1]);
                *(float2*)(out + (size_t)(v0 + r1) * FEAT + n0) = v;
            }
        }
    }
}

// ---------------- launch ----------------
extern "C" void kernel_launch(void* const* d_in, const int* in_sizes, int n_in,
                              void* d_out, int out_size) {
    const float* node_feats = (const float*)d_in[0];
    const float* edge_feats = (const float*)d_in[1];
    const int* src = (const int*)d_in[2];
    const int* dst = (const int*)d_in[3];
    const float* W1a = (const float*)d_in[4];
    const float* b1a = (const float*)d_in[5];
    const float* W1b = (const float*)d_in[6];
    const float* b1b = (const float*)d_in[7];
    const float* W2a = (const float*)d_in[8];
    const float* b2a = (const float*)d_in[9];
    const float* W2b = (const float*)d_in[10];
    const float* b2b = (const float*)d_in[11];
    float* out = (float*)d_out;

    const int n_nodes = in_sizes[0] / FEAT;
    const int n_edges = in_sizes[2];

    cudaFuncSetAttribute(edge_kernel, cudaFuncAttributeMaxDynamicSharedMemorySize,
                         DYN_BYTES);
    cudaFuncSetAttribute(node_kernel, cudaFuncAttributeMaxDynamicSharedMemorySize,
                         DYN_BYTES);

    prep_weights<<<160, 256>>>(W1a, W1b, W2a, W2b);
    init_agg_kernel<<<512, 256>>>(node_feats, n_nodes * (FEAT / 4));

    int edge_blocks = (n_edges + 63) / 64;
    edge_kernel<<<edge_blocks, 256, DYN_BYTES>>>(node_feats, edge_feats, src, dst, b1a,
                                                 b1b, n_edges);

    int node_blocks = (n_nodes + 63) / 64;
    node_kernel<<<node_blocks, 256, DYN_BYTES>>>(b2a, b2b, out, n_nodes);
}

// round 17
// speedup vs baseline: 1.8821x; 1.2076x over previous
#include <cuda_runtime.h>
#include <cuda_fp16.h>

#define FEAT 128
#define MAX_NODES 50000

typedef unsigned int u32;

// ---------------- device scratch ----------------
static __device__ float g_agg[(size_t)MAX_NODES * FEAT];
// fp16 weight fragments, hi/lo interleaved per 16B:
// u32 idx = chunk*8192 + ((ks*16 + nf)*32 + lane)*4 + split*2 + r
static __device__ __align__(16) u32 g_w1a_f[32768];  // K=256: 4 chunks
static __device__ __align__(16) u32 g_w1b_f[16384];  // K=128: 2 chunks
static __device__ __align__(16) u32 g_w2a_f[16384];
static __device__ __align__(16) u32 g_w2b_f[16384];

// ---- smem geometry (dynamic, bytes), M=64 per CTA ----
// A fp16-hi tile: @0, 64 x 144B = 9216
// fp32 stage:     @9216, 64 x 272B = 17408   -> 26624
// weights:        wb @26624 (32KB interleaved) -> 59392
// hidden fragments (16KB) alias [0..16384) during layer 2.
#define A_STRIDE   144
#define STG_OFF    9216
#define STG_STRIDE 272
#define WB_OFF     26624
#define DYN_BYTES  59392

// ---------------- helpers ----------------
__device__ __forceinline__ u32 smem_u32(const void* p) {
    u32 a;
    asm("{ .reg .u64 t; cvta.to.shared.u64 t, %1; cvt.u32.u64 %0, t; }" : "=r"(a) : "l"(p));
    return a;
}
__device__ __forceinline__ void lds128(u32 a, u32* r) {
    asm volatile("ld.shared.v4.b32 {%0,%1,%2,%3}, [%4];"
                 : "=r"(r[0]), "=r"(r[1]), "=r"(r[2]), "=r"(r[3]) : "r"(a));
}
__device__ __forceinline__ void sts64(u32 a, u32 x, u32 y) {
    asm volatile("st.shared.v2.b32 [%0], {%1,%2};" ::"r"(a), "r"(x), "r"(y));
}
__device__ __forceinline__ void sts128(u32 a, const u32* r) {
    asm volatile("st.shared.v4.b32 [%0], {%1,%2,%3,%4};" ::"r"(a), "r"(r[0]), "r"(r[1]),
                 "r"(r[2]), "r"(r[3]));
}
// ldmatrix x4: A m16k16 fragment from row-major fp16 tile
__device__ __forceinline__ void ldmA(u32 a, u32* r) {
    asm volatile("ldmatrix.sync.aligned.m8n8.x4.shared.b16 {%0,%1,%2,%3}, [%4];"
                 : "=r"(r[0]), "=r"(r[1]), "=r"(r[2]), "=r"(r[3]) : "r"(a));
}

__device__ __forceinline__ void mma16816(float c[4], const u32 a[4], u32 b0, u32 b1) {
    asm volatile(
        "mma.sync.aligned.m16n8k16.row.col.f32.f16.f16.f32 "
        "{%0,%1,%2,%3}, {%4,%5,%6,%7}, {%8,%9}, {%0,%1,%2,%3};"
        : "+f"(c[0]), "+f"(c[1]), "+f"(c[2]), "+f"(c[3])
        : "r"(a[0]), "r"(a[1]), "r"(a[2]), "r"(a[3]), "r"(b0), "r"(b1));
}

// pack two fp32 -> fp16x2 (x in low half)
__device__ __forceinline__ u32 pk_h2(float x, float y) {
    __half2 h = __floats2half2_rn(x, y);
    return *reinterpret_cast<u32*>(&h);
}
// fp32 pair -> fp16x2 hi + fp16x2 lo (for weights)
__device__ __forceinline__ void split2h(float x, float y, u32& H, u32& L) {
    __half hx = __float2half_rn(x), hy = __float2half_rn(y);
    __half lx = __float2half_rn(x - __half2float(hx));
    __half ly = __float2half_rn(y - __half2float(hy));
    __half2 hh = __halves2half2(hx, hy), ll = __halves2half2(lx, ly);
    H = *reinterpret_cast<u32*>(&hh);
    L = *reinterpret_cast<u32*>(&ll);
}

// ---- cp.async staging: each thread stages 16 fp32 (its own convert slice) ----
__device__ __forceinline__ void stage_row(const float* __restrict__ sp, u32 sd) {
#pragma unroll
    for (int q = 0; q < 4; q++) {
        asm volatile("cp.async.cg.shared.global [%0], [%1], 16;" ::"r"(sd + q * 16),
                     "l"(sp + q * 4));
    }
    asm volatile("cp.async.commit_group;");
}

// convert own staged 16 fp32 -> fp16 hi in A tile (smem -> smem)
__device__ __forceinline__ void convert_own(u32 ss, u32 dhi) {
#pragma unroll
    for (int q = 0; q < 4; q++) {
        u32 w[4];
        lds128(ss + q * 16, w);
        u32 p0 = pk_h2(__uint_as_float(w[0]), __uint_as_float(w[1]));
        u32 p1 = pk_h2(__uint_as_float(w[2]), __uint_as_float(w[3]));
        sts64(dhi + q * 8, p0, p1);
    }
}

// async-copy one 32KB interleaved weight chunk global -> smem (256 threads)
__device__ __forceinline__ void cp_w32(const u32* __restrict__ g, u32 sB, int tid) {
#pragma unroll
    for (int i = 0; i < 8; i++) {
        u32 d = sB + (u32)(tid + i * 256) * 16;
        const u32* s = g + (tid + i * 256) * 4;
        asm volatile("cp.async.cg.shared.global [%0], [%1], 16;" ::"r"(d), "l"(s));
    }
    asm volatile("cp.async.commit_group;");
}
#define CP_WAIT0() asm volatile("cp.async.wait_group 0;" ::: "memory")

// ---- layer-1 GEMM chunk: warp tile 32x32 (2 mt x 4 nf), fp16 2-term ----
// acc += A_hi*B_hi + A_hi*B_lo, K=64 per chunk.
__device__ __forceinline__ void g1_fused(u32 aHi, u32 wb, float (*acc)[4][4], int lane,
                                         int wc) {
    const u32 arow = aHi + (u32)(lane & 15) * A_STRIDE + (lane >> 4) * 16;
    const u32 bl = wb + (u32)wc * 2048 + lane * 16;
#pragma unroll
    for (int ks = 0; ks < 4; ks++) {
        u32 b[4][4];
#pragma unroll
        for (int nf = 0; nf < 4; nf++) lds128(bl + ks * 8192 + nf * 512, b[nf]);
        u32 ah[2][4];
#pragma unroll
        for (int m = 0; m < 2; m++)
            ldmA(arow + (u32)(m * 16) * A_STRIDE + ks * 32, ah[m]);
        // 2 passes of 8 independent accumulators
#pragma unroll
        for (int m = 0; m < 2; m++)
#pragma unroll
            for (int nf = 0; nf < 4; nf++)
                mma16816(acc[m][nf], ah[m], b[nf][0], b[nf][1]);
#pragma unroll
        for (int m = 0; m < 2; m++)
#pragma unroll
            for (int nf = 0; nf < 4; nf++)
                mma16816(acc[m][nf], ah[m], b[nf][2], b[nf][3]);
    }
}

// ---- layer-2 GEMM chunk: A from hidden fragments ----
// slot addr: hb + ((wr*2 + mt)*8 + kg)*512 + lane*16
__device__ __forceinline__ void g2_fused(u32 hb, u32 wb, float (*acc)[4][4], int lane,
                                         int wr, int wc, int kg0) {
    const u32 bl = wb + (u32)wc * 2048 + lane * 16;
#pragma unroll
    for (int ks = 0; ks < 4; ks++) {
        int kg = kg0 + ks;
        u32 b[4][4];
#pragma unroll
        for (int nf = 0; nf < 4; nf++) lds128(bl + ks * 8192 + nf * 512, b[nf]);
        u32 ah[2][4];
#pragma unroll
        for (int m = 0; m < 2; m++)
            lds128(hb + (u32)(((wr * 2 + m) * 8 + kg) * 512) + lane * 16, ah[m]);
#pragma unroll
        for (int m = 0; m < 2; m++)
#pragma unroll
            for (int nf = 0; nf < 4; nf++)
                mma16816(acc[m][nf], ah[m], b[nf][0], b[nf][1]);
#pragma unroll
        for (int m = 0; m < 2; m++)
#pragma unroll
            for (int nf = 0; nf < 4; nf++)
                mma16816(acc[m][nf], ah[m], b[nf][2], b[nf][3]);
    }
}

// epilogue: relu(acc + bias) -> hidden fp16 fragments (A-frag layout); zero acc
__device__ __forceinline__ void epi_hidden(float (*acc)[4][4], const float* bias, u32 hb,
                                           int lane, int wr, int wc) {
    const int c2 = (lane & 3) * 2;
#pragma unroll
    for (int mt = 0; mt < 2; mt++) {
#pragma unroll
        for (int p = 0; p < 2; p++) {
            u32 h[4];
#pragma unroll
            for (int q = 0; q < 2; q++) {
                int nf = p * 2 + q;
                int n0 = wc * 32 + nf * 8 + c2;
                float v0 = fmaxf(acc[mt][nf][0] + bias[n0], 0.0f);
                float v1 = fmaxf(acc[mt][nf][1] + bias[n0 + 1], 0.0f);
                float v2 = fmaxf(acc[mt][nf][2] + bias[n0], 0.0f);
                float v3 = fmaxf(acc[mt][nf][3] + bias[n0 + 1], 0.0f);
                h[q * 2] = pk_h2(v0, v1);
                h[q * 2 + 1] = pk_h2(v2, v3);
            }
            int kg = wc * 2 + p;
            sts128(hb + (u32)(((wr * 2 + mt) * 8 + kg) * 512) + lane * 16, h);
        }
#pragma unroll
        for (int nf = 0; nf < 4; nf++)
#pragma unroll
            for (int j = 0; j < 4; j++) acc[mt][nf][j] = 0.0f;
    }
}

// ---------------- kernel 0: weight prep (fp16 split + interleaved pack) ----------
__global__ void prep_weights(const float* __restrict__ W1a, const float* __restrict__ W1b,
                             const float* __restrict__ W2a, const float* __restrict__ W2b) {
    int total = 16384 + 3 * 8192;  // k-pair x n counts
    for (int i = blockIdx.x * blockDim.x + threadIdx.x; i < total;
         i += gridDim.x * blockDim.x) {
        int j = i;
        const float* W;
        u32* G;
        if (j < 16384) {
            W = W1a;
            G = g_w1a_f;
        } else {
            j -= 16384;
            int ws = j / 8192;
            j %= 8192;
            W = (ws == 0) ? W1b : (ws == 1) ? W2a : W2b;
            G = (ws == 0) ? g_w1b_f : (ws == 1) ? g_w2a_f : g_w2b_f;
        }
        int ke = (j >> 7) * 2, n = j & 127;
        float x0 = W[ke * 128 + n], x1 = W[(ke + 1) * 128 + n];
        u32 H, L;
        split2h(x0, x1, H, L);
        int chunk = ke >> 6, ks = (ke >> 4) & 3, r = (ke >> 3) & 1, l4 = (ke >> 1) & 3;
        int nf = n >> 3, lane = (n & 7) * 4 + l4;
        int base = chunk * 8192 + ((ks * 16 + nf) * 32 + lane) * 4 + r;
        G[base] = H;
        G[base + 2] = L;
    }
}

// ---------------- kernel 1: g_agg = node_feats ----------------
__global__ void init_agg_kernel(const float* __restrict__ node_feats, int total4) {
    int i = blockIdx.x * blockDim.x + threadIdx.x;
    int stride = gridDim.x * blockDim.x;
    const float4* s = (const float4*)node_feats;
    float4* d = (float4*)g_agg;
    for (; i < total4; i += stride) d[i] = s[i];
}

// ---------------- kernel 2: edge MLP + scatter (M=64 per CTA) ----------------
extern __shared__ char dynraw[];

__global__ __launch_bounds__(256, 3) void edge_kernel(
    const float* __restrict__ node_feats, const float* __restrict__ edge_feats,
    const int* __restrict__ src, const int* __restrict__ dst,
    const float* __restrict__ b1a, const float* __restrict__ b1b, int n_edges) {
    __shared__ int s_src[64], s_dst[64];
    __shared__ float s_ba[FEAT], s_bb[FEAT];

    const int tid = threadIdx.x;
    const int wid = tid >> 5, lane = tid & 31;
    const int wr = wid >> 2, wc = wid & 3;
    const u32 smb = smem_u32(dynraw);
    const u32 hb = smb;  // hidden fragments alias A region
    const u32 wb = smb + WB_OFF;

    const int e0 = blockIdx.x * 64;
    if (tid < 64) {
        int e = min(e0 + tid, n_edges - 1);
        s_src[tid] = __ldg(src + e);
        s_dst[tid] = __ldg(dst + e);
    }
    if (tid >= 128) {
        s_ba[tid - 128] = __ldg(b1a + tid - 128);
        s_bb[tid - 128] = __ldg(b1b + tid - 128);
    }
    __syncthreads();

    float acc[2][4][4];
#pragma unroll
    for (int mt = 0; mt < 2; mt++)
#pragma unroll
        for (int nf = 0; nf < 4; nf++)
#pragma unroll
            for (int j = 0; j < 4; j++) acc[mt][nf][j] = 0.0f;

    const int row = tid >> 2, hh = tid & 3;  // own slice: 16 floats
    const u32 sstg = smb + STG_OFF + (u32)row * STG_STRIDE + hh * 64;
    const u32 sdst = smb + (u32)row * A_STRIDE + hh * 32;
    const int erow = min(e0 + row, n_edges - 1);
    const u32 aWarp = smb + (u32)wr * 32 * A_STRIDE;

    auto rowp = [&](int c) -> const float* {
        if (c < 2) return node_feats + (size_t)s_src[row] * FEAT + c * 64 + hh * 16;
        return edge_feats + (size_t)erow * FEAT + (c - 2) * 64 + hh * 16;
    };

    // ---- prologue: stage A(0) + W(0), convert ----
    stage_row(rowp(0), sstg);
    cp_w32(g_w1a_f, wb, tid);
    CP_WAIT0();
    convert_own(sstg, sdst);
    __syncthreads();

    // ---- layer 1: K=256, 4 chunks ----
#pragma unroll 1
    for (int c = 0; c < 4; c++) {
        if (c < 3) stage_row(rowp(c + 1), sstg);  // lands during gemm
        g1_fused(aWarp, wb, acc, lane, wc);
        __syncthreads();  // A tile + weights + stage free
        if (c < 3) {
            cp_w32(g_w1a_f + (c + 1) * 8192, wb, tid);
            CP_WAIT0();
            convert_own(sstg, sdst);
            __syncthreads();
        }
    }

    // ---- epilogue 1: issue layer-2 chunk-0 weights; relu -> hidden fragments ----
    cp_w32(g_w1b_f, wb, tid);
    epi_hidden(acc, s_ba, hb, lane, wr, wc);
    CP_WAIT0();
    __syncthreads();

    // ---- layer 2: K=128, 2 chunks ----
    g2_fused(hb, wb, acc, lane, wr, wc, 0);
    __syncthreads();
    cp_w32(g_w1b_f + 8192, wb, tid);
    CP_WAIT0();
    __syncthreads();
    g2_fused(hb, wb, acc, lane, wr, wc, 4);

    // ---- epilogue 2: scatter (acc + b1b) into g_agg ----
    const int rr = lane >> 2, c2 = (lane & 3) * 2;
#pragma unroll
    for (int mt = 0; mt < 2; mt++) {
        const int r0 = wr * 32 + mt * 16 + rr, r1 = r0 + 8;
        float* p0 = g_agg + (size_t)s_dst[r0] * FEAT;
        float* p1 = g_agg + (size_t)s_dst[r1] * FEAT;
        const bool ok0 = (e0 + r0 < n_edges), ok1 = (e0 + r1 < n_edges);
#pragma unroll
        for (int nf = 0; nf < 4; nf++) {
            int n0 = wc * 32 + nf * 8 + c2;
            if (ok0) {
                atomicAdd(p0 + n0, acc[mt][nf][0] + s_bb[n0]);
                atomicAdd(p0 + n0 + 1, acc[mt][nf][1] + s_bb[n0 + 1]);
            }
            if (ok1) {
                atomicAdd(p1 + n0, acc[mt][nf][2] + s_bb[n0]);
                atomicAdd(p1 + n0 + 1, acc[mt][nf][3] + s_bb[n0 + 1]);
            }
        }
    }
}

// ---------------- kernel 3: node MLP (M=64 per CTA) ----------------
__global__ __launch_bounds__(256, 3) void node_kernel(const float* __restrict__ b2a,
                                                      const float* __restrict__ b2b,
                                                      float* __restrict__ out, int n_nodes) {
    __shared__ float s_ba[FEAT], s_bb[FEAT];

    const int tid = threadIdx.x;
    const int wid = tid >> 5, lane = tid & 31;
    const int wr = wid >> 2, wc = wid & 3;
    const u32 smb = smem_u32(dynraw);
    const u32 hb = smb;
    const u32 wb = smb + WB_OFF;

    const int v0 = blockIdx.x * 64;
    if (tid < 128) {
        s_ba[tid] = __ldg(b2a + tid);
        s_bb[tid] = __ldg(b2b + tid);
    }
    __syncthreads();

    float acc[2][4][4];
#pragma unroll
    for (int mt = 0; mt < 2; mt++)
#pragma unroll
        for (int nf = 0; nf < 4; nf++)
#pragma unroll
            for (int j = 0; j < 4; j++) acc[mt][nf][j] = 0.0f;

    const int row = tid >> 2, hh = tid & 3;
    const u32 sstg = smb + STG_OFF + (u32)row * STG_STRIDE + hh * 64;
    const u32 sdst = smb + (u32)row * A_STRIDE + hh * 32;
    const size_t grow = (size_t)min(v0 + row, n_nodes - 1) * FEAT;
    const u32 aWarp = smb + (u32)wr * 32 * A_STRIDE;

    // ---- prologue ----
    stage_row(g_agg + grow + hh * 16, sstg);
    cp_w32(g_w2a_f, wb, tid);
    CP_WAIT0();
    convert_own(sstg, sdst);
    __syncthreads();

    // ---- layer 1: K=128, 2 chunks ----
#pragma unroll 1
    for (int c = 0; c < 2; c++) {
        if (c < 1) stage_row(g_agg + grow + 64 + hh * 16, sstg);
        g1_fused(aWarp, wb, acc, lane, wc);
        __syncthreads();
        if (c < 1) {
            cp_w32(g_w2a_f + 8192, wb, tid);
            CP_WAIT0();
            convert_own(sstg, sdst);
            __syncthreads();
        }
    }

    // ---- epilogue 1 ----
    cp_w32(g_w2b_f, wb, tid);
    epi_hidden(acc, s_ba, hb, lane, wr, wc);
    CP_WAIT0();
    __syncthreads();

    // ---- layer 2: K=128, 2 chunks ----
    g2_fused(hb, wb, acc, lane, wr, wc, 0);
    __syncthreads();
    cp_w32(g_w2b_f + 8192, wb, tid);
    CP_WAIT0();
    __syncthreads();
    g2_fused(hb, wb, acc, lane, wr, wc, 4);

    // ---- epilogue 2: out = acc + b2b ----
    const int rr = lane >> 2, c2 = (lane & 3) * 2;
#pragma unroll
    for (int mt = 0; mt < 2; mt++) {
        const int r0 = wr * 32 + mt * 16 + rr, r1 = r0 + 8;
#pragma unroll
        for (int nf = 0; nf < 4; nf++) {
            int n0 = wc * 32 + nf * 8 + c2;
            if (v0 + r0 < n_nodes) {
                float2 v = make_float2(acc[mt][nf][0] + s_bb[n0],
                                       acc[mt][nf][1] + s_bb[n0 + 1]);
                *(float2*)(out + (size_t)(v0 + r0) * FEAT + n0) = v;
            }
            if (v0 + r1 < n_nodes) {
                float2 v = make_float2(acc[mt][nf][2] + s_bb[n0],
                                       acc[mt][nf][3] + s_bb[n0 + 1]);
                *(float2*)(out + (size_t)(v0 + r1) * FEAT + n0) = v;
            }
        }
    }
}

// ---------------- launch ----------------
extern "C" void kernel_launch(void* const* d_in, const int* in_sizes, int n_in,
                              void* d_out, int out_size) {
    const float* node_feats = (const float*)d_in[0];
    const float* edge_feats = (const float*)d_in[1];
    const int* src = (const int*)d_in[2];
    const int* dst = (const int*)d_in[3];
    const float* W1a = (const float*)d_in[4];
    const float* b1a = (const float*)d_in[5];
    const float* W1b = (const float*)d_in[6];
    const float* b1b = (const float*)d_in[7];
    const float* W2a = (const float*)d_in[8];
    const float* b2a = (const float*)d_in[9];
    const float* W2b = (const float*)d_in[10];
    const float* b2b = (const float*)d_in[11];
    float* out = (float*)d_out;

    const int n_nodes = in_sizes[0] / FEAT;
    const int n_edges = in_sizes[2];

    cudaFuncSetAttribute(edge_kernel, cudaFuncAttributeMaxDynamicSharedMemorySize,
                         DYN_BYTES);
    cudaFuncSetAttribute(node_kernel, cudaFuncAttributeMaxDynamicSharedMemorySize,
                         DYN_BYTES);

    prep_weights<<<160, 256>>>(W1a, W1b, W2a, W2b);
    init_agg_kernel<<<512, 256>>>(node_feats, n_nodes * (FEAT / 4));

    int edge_blocks = (n_edges + 63) / 64;
    edge_kernel<<<edge_blocks, 256, DYN_BYTES>>>(node_feats, edge_feats, src, dst, b1a,
                                                 b1b, n_edges);

    int node_blocks = (n_nodes + 63) / 64;
    node_kernel<<<node_blocks, 256, DYN_BYTES>>>(b2a, b2b, out, n_nodes);
}